// round 8
// baseline (speedup 1.0000x reference)
#include <cuda_runtime.h>
#include <math.h>

// Problem constants: B=64, J=21, D=H=W=64
#define NUM_J   21
#define NUM_B   64
#define NJOINT  (NUM_B * NUM_J)         // 1344 (b,j) volumes
#define NCOARSE 1280                    // volumes processed as half-volumes
#define NFINE   (NJOINT - NCOARSE)      // 64 volumes processed as eighth-volumes
#define NBLK_C  (NCOARSE * 2)           // 2560 coarse blocks (32 planes each)
#define NBLK_F  (NFINE * 8)             // 512 fine blocks (8 planes each)
#define NBLK    (NBLK_C + NBLK_F)       // 3072 total
#define VOL     (64 * 64 * 64)          // 262144 elements per volume
#define LOG2E   1.4426950408889634f

__device__ float4       g_part[NJOINT * 8]; // up to 8 partial slots per volume
                                            // (unused slots stay zero from static init)
__device__ unsigned int g_counter;          // zero-init; reset by last block

// Compile-time-specialized streaming loop: ND is a constant so ptxas fully
// structures the unroll and front-batches the loads (identical to the R5
// codegen for ND=32).
template <int ND>
__device__ __forceinline__ void mainloop(const float4* __restrict__ pa,
                                         const float4* __restrict__ pb,
                                         int d0, float wbf, float hf,
                                         float& S, float& Sx, float& Sy, float& Sz) {
    #pragma unroll 4
    for (int d = 0; d < ND; ++d) {
        float4 va = __ldcs(pa + d * 1024);
        float4 vb = __ldcs(pb + d * 1024);

        float a0 = exp2f(va.x * LOG2E);
        float a1 = exp2f(va.y * LOG2E);
        float a2 = exp2f(va.z * LOG2E);
        float a3 = exp2f(va.w * LOG2E);
        float b0 = exp2f(vb.x * LOG2E);
        float b1 = exp2f(vb.y * LOG2E);
        float b2 = exp2f(vb.z * LOG2E);
        float b3 = exp2f(vb.w * LOG2E);

        float SqA = (a0 + a1) + (a2 + a3);
        float SqB = (b0 + b1) + (b2 + b3);
        float Sq  = SqA + SqB;

        float tw = fmaf(2.0f, a2, a1);
        tw       = fmaf(3.0f, a3, tw);
        tw       = fmaf(2.0f, b2, tw + b1);
        tw       = fmaf(3.0f, b3, tw);            // intra-float4 x offsets, both halves

        S  += Sq;
        Sx += tw;
        Sx  = fmaf(wbf, Sq, Sx);
        Sy  = fmaf(hf,  Sq, Sy);
        Sy  = fmaf(32.0f, SqB, Sy);               // B half sits 32 rows lower
        Sz  = fmaf((float)(d0 + d), Sq, Sz);
    }
}

__global__ __launch_bounds__(512, 3)
void jll_fused_kernel(const float* __restrict__ hm,
                      const float* __restrict__ gt,
                      const float* __restrict__ vis,
                      float* __restrict__ out) {
    const int t   = threadIdx.x;            // 0..511
    const int bid = blockIdx.x;              // 0..3071

    // work decode: coarse = 32-plane half-volume, fine (tail) = 8-plane slab
    int bj, d0, slot;
    bool fine = (bid >= NBLK_C);
    if (!fine) {
        bj   = bid >> 1;
        slot = bid & 1;
        d0   = slot * 32;
    } else {
        int r = bid - NBLK_C;
        bj   = NCOARSE + (r >> 3);
        slot = r & 7;
        d0   = slot * 8;
    }

    const float4* __restrict__ pa =
        (const float4*)(hm + (size_t)bj * VOL) + (size_t)d0 * 1024 + t;
    const float4* __restrict__ pb = pa + 512;

    // thread owns float4 #t and #(t+512) of each 4096-elem (h,w) plane:
    // same w, h shifted by +32 for the B stream.
    const int   elem = 4 * t;
    const float wbf  = (float)(elem & 63);
    const float hf   = (float)(elem >> 6);

    // Input ~N(0,1): no max-subtraction needed; branch-free streaming.
    float S = 0.f, Sx = 0.f, Sy = 0.f, Sz = 0.f;

    if (!fine) mainloop<32>(pa, pb, d0, wbf, hf, S, Sx, Sy, Sz);
    else       mainloop<8> (pa, pb, d0, wbf, hf, S, Sx, Sy, Sz);

    // warp butterfly reduce
    #pragma unroll
    for (int off = 16; off > 0; off >>= 1) {
        S  += __shfl_xor_sync(0xFFFFFFFFu, S,  off);
        Sx += __shfl_xor_sync(0xFFFFFFFFu, Sx, off);
        Sy += __shfl_xor_sync(0xFFFFFFFFu, Sy, off);
        Sz += __shfl_xor_sync(0xFFFFFFFFu, Sz, off);
    }

    __shared__ float sS[16], sSx[16], sSy[16], sSz[16];
    __shared__ bool  sIsLast;
    const int warp = t >> 5;
    const int lane = t & 31;
    if (lane == 0) { sS[warp] = S; sSx[warp] = Sx; sSy[warp] = Sy; sSz[warp] = Sz; }
    __syncthreads();

    if (warp == 0) {
        const bool valid = lane < 16;
        S  = valid ? sS[lane]  : 0.f;
        Sx = valid ? sSx[lane] : 0.f;
        Sy = valid ? sSy[lane] : 0.f;
        Sz = valid ? sSz[lane] : 0.f;
        #pragma unroll
        for (int off = 8; off > 0; off >>= 1) {
            S  += __shfl_xor_sync(0xFFFFFFFFu, S,  off);
            Sx += __shfl_xor_sync(0xFFFFFFFFu, Sx, off);
            Sy += __shfl_xor_sync(0xFFFFFFFFu, Sy, off);
            Sz += __shfl_xor_sync(0xFFFFFFFFu, Sz, off);
        }
        if (lane == 0) {
            // coarse blocks own slots {0,1}; fine blocks own slots {0..7}.
            // Distinct volumes, so no slot collision; unused slots stay 0.
            int pslot = fine ? slot : slot;   // slot already encodes position
            g_part[(size_t)bj * 8 + pslot] = make_float4(S, Sx, Sy, Sz);
            __threadfence();
            unsigned int done = atomicAdd(&g_counter, 1u);
            sIsLast = (done == (unsigned)(NBLK - 1));
        }
    }
    __syncthreads();

    // last block: merge partial slots, compute coords + loss, write scalar
    if (sIsLast) {
        float s = 0.0f;
        for (int i = t; i < NJOINT; i += 512) {
            const float4* gp = g_part + (size_t)i * 8;
            float4 acc = gp[0];
            #pragma unroll
            for (int k = 1; k < 8; ++k) {
                float4 v = gp[k];
                acc.x += v.x; acc.y += v.y; acc.z += v.z; acc.w += v.w;
            }
            float invS = 1.0f / acc.x;
            float x = acc.y * invS * 0.015625f - 0.5f;   // /64 - 0.5
            float y = acc.z * invS * 0.015625f - 0.5f;
            float z = acc.w * invS * 0.015625f - 0.5f;

            int b = i / NUM_J;
            int j = i - b * NUM_J;
            const float* g = gt  + b * (NUM_J * 3) + j * 3;
            const float* w = vis + b * (NUM_J * 3) + j * 3;
            s += fabsf(x - g[0]) * w[0]
               + fabsf(y - g[1]) * w[1]
               + fabsf(z - g[2]) * w[2];
        }

        #pragma unroll
        for (int off = 16; off > 0; off >>= 1)
            s += __shfl_xor_sync(0xFFFFFFFFu, s, off);

        __shared__ float sm[16];
        if (lane == 0) sm[warp] = s;
        __syncthreads();
        if (warp == 0) {
            s = (lane < 16) ? sm[lane] : 0.f;
            #pragma unroll
            for (int off = 8; off > 0; off >>= 1)
                s += __shfl_xor_sync(0xFFFFFFFFu, s, off);
            if (lane == 0) {
                out[0] = s * (1.0f / (float)NUM_B);
                g_counter = 0u;   // reset for next graph replay
            }
        }
    }
}

extern "C" void kernel_launch(void* const* d_in, const int* in_sizes, int n_in,
                              void* d_out, int out_size) {
    const float* hm  = (const float*)d_in[0];   // heatmap_out [64, 1344, 64, 64]
    const float* gt  = (const float*)d_in[1];   // gt_coord   [64, 63]
    const float* vis = (const float*)d_in[2];   // gt_vis     [64, 63]
    float* out = (float*)d_out;

    jll_fused_kernel<<<NBLK, 512>>>(hm, gt, vis, out);
}

// round 9
// speedup vs baseline: 1.0234x; 1.0234x over previous
#include <cuda_runtime.h>
#include <math.h>

// Problem constants: B=64, J=21, D=H=W=64
#define NUM_J  21
#define NUM_B  64
#define NJOINT (NUM_B * NUM_J)          // 1344 (b,j) volumes
#define NBLK   (NJOINT * 2)             // 2688 half-volume blocks
#define VOL    (64 * 64 * 64)           // 262144 elements per volume
#define LOG2E  1.4426950408889634f

__device__ float        g_part[NBLK * 4];   // S, Sx, Sy, Sz per half-volume block
__device__ unsigned int g_counter;          // zero-init; reset by last block

__global__ __launch_bounds__(512, 3)
void jll_fused_kernel(const float* __restrict__ hm,
                      const float* __restrict__ gt,
                      const float* __restrict__ vis,
                      float* __restrict__ out) {
    const int t    = threadIdx.x;           // 0..511
    const int blk  = blockIdx.x;            // 0..2687
    const int bj   = blk >> 1;              // volume index
    const int half = blk & 1;               // d half: 0 -> d[0,32), 1 -> d[32,64)
    const int d0   = half * 32;

    const float4* __restrict__ pa =
        (const float4*)(hm + (size_t)bj * VOL) + (size_t)d0 * 1024 + t;
    const float4* __restrict__ pb = pa + 512;

    // thread owns float4 #t and #(t+512) of each 4096-elem (h,w) plane.
    // elemB = elemA + 2048 -> same w, h shifted by +32.
    const int   elem = 4 * t;
    const float wbf  = (float)(elem & 63);
    const float hf   = (float)(elem >> 6);

    // Input ~N(0,1): no max-subtraction needed; branch-free streaming.
    // Loop-invariant weights (wbf, hf, +32 row offset) are deferred:
    //   Sx = Stw + wbf*S ;  Sy = hf*S + 32*SB
    float S = 0.f, SB = 0.f, Stw = 0.f, Sz = 0.f;

    #pragma unroll 4
    for (int d = 0; d < 32; ++d) {
        float4 va = __ldcs(pa + d * 1024);
        float4 vb = __ldcs(pb + d * 1024);

        float a0 = exp2f(va.x * LOG2E);
        float a1 = exp2f(va.y * LOG2E);
        float a2 = exp2f(va.z * LOG2E);
        float a3 = exp2f(va.w * LOG2E);
        float b0 = exp2f(vb.x * LOG2E);
        float b1 = exp2f(vb.y * LOG2E);
        float b2 = exp2f(vb.z * LOG2E);
        float b3 = exp2f(vb.w * LOG2E);

        float SqA = (a0 + a1) + (a2 + a3);
        float SqB = (b0 + b1) + (b2 + b3);
        float Sq  = SqA + SqB;

        float tw = fmaf(2.0f, a2, a1);
        tw       = fmaf(3.0f, a3, tw);
        tw       = fmaf(2.0f, b2, tw + b1);
        tw       = fmaf(3.0f, b3, tw);            // intra-float4 x offsets, both halves

        S   += Sq;
        SB  += SqB;
        Stw += tw;
        Sz   = fmaf((float)(d0 + d), Sq, Sz);
    }

    // apply deferred loop-invariant weights
    float Sx = fmaf(wbf, S, Stw);
    float Sy = fmaf(hf,  S, 32.0f * SB);

    // warp butterfly reduce
    #pragma unroll
    for (int off = 16; off > 0; off >>= 1) {
        S  += __shfl_xor_sync(0xFFFFFFFFu, S,  off);
        Sx += __shfl_xor_sync(0xFFFFFFFFu, Sx, off);
        Sy += __shfl_xor_sync(0xFFFFFFFFu, Sy, off);
        Sz += __shfl_xor_sync(0xFFFFFFFFu, Sz, off);
    }

    __shared__ float sS[16], sSx[16], sSy[16], sSz[16];
    __shared__ bool  sIsLast;
    const int warp = t >> 5;
    const int lane = t & 31;
    if (lane == 0) { sS[warp] = S; sSx[warp] = Sx; sSy[warp] = Sy; sSz[warp] = Sz; }
    __syncthreads();

    if (warp == 0) {
        const bool valid = lane < 16;
        S  = valid ? sS[lane]  : 0.f;
        Sx = valid ? sSx[lane] : 0.f;
        Sy = valid ? sSy[lane] : 0.f;
        Sz = valid ? sSz[lane] : 0.f;
        #pragma unroll
        for (int off = 8; off > 0; off >>= 1) {
            S  += __shfl_xor_sync(0xFFFFFFFFu, S,  off);
            Sx += __shfl_xor_sync(0xFFFFFFFFu, Sx, off);
            Sy += __shfl_xor_sync(0xFFFFFFFFu, Sy, off);
            Sz += __shfl_xor_sync(0xFFFFFFFFu, Sz, off);
        }
        if (lane == 0) {
            float* gp = g_part + (size_t)blk * 4;
            gp[0] = S; gp[1] = Sx; gp[2] = Sy; gp[3] = Sz;

            __threadfence();
            unsigned int done = atomicAdd(&g_counter, 1u);
            sIsLast = (done == (unsigned)(NBLK - 1));
        }
    }
    __syncthreads();

    // last block: merge half-volume partials, compute coords + loss, write scalar
    if (sIsLast) {
        float s = 0.0f;
        for (int i = t; i < NJOINT; i += 512) {
            const float* gp0 = g_part + (size_t)(2 * i)     * 4;
            const float* gp1 = g_part + (size_t)(2 * i + 1) * 4;
            float S4  = gp0[0] + gp1[0];
            float Sx4 = gp0[1] + gp1[1];
            float Sy4 = gp0[2] + gp1[2];
            float Sz4 = gp0[3] + gp1[3];

            float invS = 1.0f / S4;
            float x = Sx4 * invS * 0.015625f - 0.5f;   // /64 - 0.5
            float y = Sy4 * invS * 0.015625f - 0.5f;
            float z = Sz4 * invS * 0.015625f - 0.5f;

            int b = i / NUM_J;
            int j = i - b * NUM_J;
            const float* g = gt  + b * (NUM_J * 3) + j * 3;
            const float* w = vis + b * (NUM_J * 3) + j * 3;
            s += fabsf(x - g[0]) * w[0]
               + fabsf(y - g[1]) * w[1]
               + fabsf(z - g[2]) * w[2];
        }

        #pragma unroll
        for (int off = 16; off > 0; off >>= 1)
            s += __shfl_xor_sync(0xFFFFFFFFu, s, off);

        __shared__ float sm[16];
        if (lane == 0) sm[warp] = s;
        __syncthreads();
        if (warp == 0) {
            s = (lane < 16) ? sm[lane] : 0.f;
            #pragma unroll
            for (int off = 8; off > 0; off >>= 1)
                s += __shfl_xor_sync(0xFFFFFFFFu, s, off);
            if (lane == 0) {
                out[0] = s * (1.0f / (float)NUM_B);
                g_counter = 0u;   // reset for next graph replay
            }
        }
    }
}

extern "C" void kernel_launch(void* const* d_in, const int* in_sizes, int n_in,
                              void* d_out, int out_size) {
    const float* hm  = (const float*)d_in[0];   // heatmap_out [64, 1344, 64, 64]
    const float* gt  = (const float*)d_in[1];   // gt_coord   [64, 63]
    const float* vis = (const float*)d_in[2];   // gt_vis     [64, 63]
    float* out = (float*)d_out;

    jll_fused_kernel<<<NBLK, 512>>>(hm, gt, vis, out);
}